// round 5
// baseline (speedup 1.0000x reference)
#include <cuda_runtime.h>
#include <math.h>

// Problem shape (fixed by the dataset)
#define B_    16
#define S_    8192
#define QDIM  1024
#define KDIM  256
#define FLOAT_MIN_V (-100000.0f)

#define CHUNKS 64
#define SCHUNK (S_ / CHUNKS)   // 128

// Scratch (no allocations allowed in kernel_launch)
__device__ float g_qp[B_ * KDIM];                    // projected query + bias, [B,K]
__device__ float g_partial[B_ * CHUNKS * KDIM];      // per-chunk ctx partials

// ---------------------------------------------------------------------------
// Kernel 1: qp[b,k] = b_attr[k] + sum_q query[b,q] * W[k,q]
// one warp per (b,k); W row contiguous over q -> coalesced float4 loads
// ---------------------------------------------------------------------------
__global__ void k_proj(const float* __restrict__ query,
                       const float* __restrict__ W,
                       const float* __restrict__ bvec)
{
    int gw   = (blockIdx.x * blockDim.x + threadIdx.x) >> 5;
    int lane = threadIdx.x & 31;
    if (gw >= B_ * KDIM) return;
    int b = gw / KDIM;
    int k = gw % KDIM;

    const float4* qrow = (const float4*)(query + (size_t)b * QDIM);
    const float4* wrow = (const float4*)(W + (size_t)k * QDIM);

    float acc = 0.f;
#pragma unroll
    for (int j = 0; j < QDIM / (32 * 4); j++) {      // 8 iters
        float4 q4 = qrow[lane + j * 32];
        float4 w4 = wrow[lane + j * 32];
        acc += q4.x * w4.x + q4.y * w4.y + q4.z * w4.z + q4.w * w4.w;
    }
#pragma unroll
    for (int o = 16; o; o >>= 1) acc += __shfl_xor_sync(0xFFFFFFFFu, acc, o);
    if (lane == 0) g_qp[b * KDIM + k] = acc + bvec[k];
}

// ---------------------------------------------------------------------------
// Kernel 2: energies[b,s] = mask*dot(tanh(keys[b,s,:]+qp[b,:]), V) + (1-mask)*MIN
// one warp per (b,s) row; K=256 -> 2 float4 loads per lane
// writes into the scores region of d_out (softmax done in place later)
// ---------------------------------------------------------------------------
__global__ void k_energy(const float* __restrict__ keys,
                         const float* __restrict__ mask,
                         const float* __restrict__ Vvec,
                         float* __restrict__ energies)
{
    int gw   = (blockIdx.x * blockDim.x + threadIdx.x) >> 5;
    int lane = threadIdx.x & 31;
    if (gw >= B_ * S_) return;
    int b = gw / S_;

    const float* row = keys + (size_t)gw * KDIM;
    const float* qp  = g_qp + b * KDIM;

    // Batch both key loads up front for MLP=2 per lane (64 lines/warp in flight)
    float4 kv0 = *(const float4*)(row + lane * 4);
    float4 kv1 = *(const float4*)(row + lane * 4 + 128);
    float4 qv0 = *(const float4*)(qp + lane * 4);
    float4 qv1 = *(const float4*)(qp + lane * 4 + 128);
    float4 vv0 = *(const float4*)(Vvec + lane * 4);
    float4 vv1 = *(const float4*)(Vvec + lane * 4 + 128);

    float acc = 0.f;
    acc += tanhf(kv0.x + qv0.x) * vv0.x;
    acc += tanhf(kv0.y + qv0.y) * vv0.y;
    acc += tanhf(kv0.z + qv0.z) * vv0.z;
    acc += tanhf(kv0.w + qv0.w) * vv0.w;
    acc += tanhf(kv1.x + qv1.x) * vv1.x;
    acc += tanhf(kv1.y + qv1.y) * vv1.y;
    acc += tanhf(kv1.z + qv1.z) * vv1.z;
    acc += tanhf(kv1.w + qv1.w) * vv1.w;

#pragma unroll
    for (int o = 16; o; o >>= 1) acc += __shfl_xor_sync(0xFFFFFFFFu, acc, o);

    if (lane == 0) {
        float m = mask[gw];
        energies[gw] = m * acc + (1.0f - m) * FLOAT_MIN_V;
    }
}

// ---------------------------------------------------------------------------
// Kernel 3: in-place softmax over S per batch. One block of 1024 per batch,
// 8 elements per thread.
// ---------------------------------------------------------------------------
__global__ void k_softmax(float* __restrict__ scores)
{
    __shared__ float red[32];
    int b   = blockIdx.x;
    int tid = threadIdx.x;
    float* e = scores + (size_t)b * S_;

    float v[8];
    float mx = -INFINITY;
#pragma unroll
    for (int i = 0; i < 8; i++) {
        v[i] = e[tid + i * 1024];
        mx = fmaxf(mx, v[i]);
    }
    // block max
#pragma unroll
    for (int o = 16; o; o >>= 1) mx = fmaxf(mx, __shfl_xor_sync(0xFFFFFFFFu, mx, o));
    if ((tid & 31) == 0) red[tid >> 5] = mx;
    __syncthreads();
    if (tid < 32) {
        float t = red[tid];
#pragma unroll
        for (int o = 16; o; o >>= 1) t = fmaxf(t, __shfl_xor_sync(0xFFFFFFFFu, t, o));
        red[tid] = t;
    }
    __syncthreads();
    mx = red[0];

    float sum = 0.f;
#pragma unroll
    for (int i = 0; i < 8; i++) {
        v[i] = __expf(v[i] - mx);
        sum += v[i];
    }
    __syncthreads();   // red[] reuse
    // block sum
#pragma unroll
    for (int o = 16; o; o >>= 1) sum += __shfl_xor_sync(0xFFFFFFFFu, sum, o);
    if ((tid & 31) == 0) red[tid >> 5] = sum;
    __syncthreads();
    if (tid < 32) {
        float t = red[tid];
#pragma unroll
        for (int o = 16; o; o >>= 1) t += __shfl_xor_sync(0xFFFFFFFFu, t, o);
        red[tid] = t;
    }
    __syncthreads();
    float inv = 1.0f / red[0];

#pragma unroll
    for (int i = 0; i < 8; i++) e[tid + i * 1024] = v[i] * inv;
}

// ---------------------------------------------------------------------------
// Kernel 4: ctx partials. One block per (b, s-chunk); thread = one k column.
// 8 independent accumulators -> 8 outstanding DRAM loads per thread.
// ---------------------------------------------------------------------------
__global__ void k_ctx_partial(const float* __restrict__ values,
                              const float* __restrict__ scores)
{
    int b = blockIdx.x / CHUNKS;
    int c = blockIdx.x % CHUNKS;
    int k = threadIdx.x;                 // 0..255
    int s0 = c * SCHUNK;

    __shared__ float sc[SCHUNK];
    for (int i = threadIdx.x; i < SCHUNK; i += blockDim.x)
        sc[i] = scores[(size_t)b * S_ + s0 + i];
    __syncthreads();

    const float* vp = values + ((size_t)b * S_ + s0) * KDIM + k;

    float a0 = 0.f, a1 = 0.f, a2 = 0.f, a3 = 0.f;
    float a4 = 0.f, a5 = 0.f, a6 = 0.f, a7 = 0.f;
#pragma unroll 2
    for (int i = 0; i < SCHUNK; i += 8) {
        float v0 = vp[(size_t)(i + 0) * KDIM];
        float v1 = vp[(size_t)(i + 1) * KDIM];
        float v2 = vp[(size_t)(i + 2) * KDIM];
        float v3 = vp[(size_t)(i + 3) * KDIM];
        float v4 = vp[(size_t)(i + 4) * KDIM];
        float v5 = vp[(size_t)(i + 5) * KDIM];
        float v6 = vp[(size_t)(i + 6) * KDIM];
        float v7 = vp[(size_t)(i + 7) * KDIM];
        a0 += v0 * sc[i + 0];
        a1 += v1 * sc[i + 1];
        a2 += v2 * sc[i + 2];
        a3 += v3 * sc[i + 3];
        a4 += v4 * sc[i + 4];
        a5 += v5 * sc[i + 5];
        a6 += v6 * sc[i + 6];
        a7 += v7 * sc[i + 7];
    }
    g_partial[((size_t)b * CHUNKS + c) * KDIM + k] =
        ((a0 + a1) + (a2 + a3)) + ((a4 + a5) + (a6 + a7));
}

// ---------------------------------------------------------------------------
// Kernel 5: reduce partials -> ctx
// ---------------------------------------------------------------------------
__global__ void k_ctx_reduce(float* __restrict__ ctx)
{
    int b = blockIdx.x;
    int k = threadIdx.x;
    float acc = 0.f;
#pragma unroll
    for (int c = 0; c < CHUNKS; c++)
        acc += g_partial[((size_t)b * CHUNKS + c) * KDIM + k];
    ctx[b * KDIM + k] = acc;
}

// ---------------------------------------------------------------------------
// Launch
// inputs (metadata order): query, keys, values, kv_mask, W_attr, b_attr, V_attr
// output: [scores (B*S) | ctx (B*K)]
// ---------------------------------------------------------------------------
extern "C" void kernel_launch(void* const* d_in, const int* in_sizes, int n_in,
                              void* d_out, int out_size)
{
    const float* query = (const float*)d_in[0];
    const float* keys  = (const float*)d_in[1];
    const float* values= (const float*)d_in[2];
    const float* mask  = (const float*)d_in[3];
    const float* W     = (const float*)d_in[4];
    const float* bvec  = (const float*)d_in[5];
    const float* Vvec  = (const float*)d_in[6];

    float* out    = (float*)d_out;
    float* scores = out;                     // B*S
    float* ctx    = out + (size_t)B_ * S_;   // B*K

    // 1) query projection: B*K warps, 8 warps/block
    {
        int warps = B_ * KDIM;
        int blocks = (warps * 32 + 255) / 256;
        k_proj<<<blocks, 256>>>(query, W, bvec);
    }
    // 2) energies: B*S warps, 8 warps/block
    {
        int warps = B_ * S_;
        int blocks = (warps * 32 + 255) / 256;
        k_energy<<<blocks, 256>>>(keys, mask, Vvec, scores);
    }
    // 3) softmax in place
    k_softmax<<<B_, 1024>>>(scores);
    // 4) ctx partials
    k_ctx_partial<<<B_ * CHUNKS, KDIM>>>(values, scores);
    // 5) reduce
    k_ctx_reduce<<<B_, KDIM>>>(ctx);
}

// round 7
// speedup vs baseline: 1.1774x; 1.1774x over previous
#include <cuda_runtime.h>
#include <math.h>

// Problem shape (fixed by the dataset)
#define B_    16
#define S_    8192
#define QDIM  1024
#define KDIM  256
#define FLOAT_MIN_V (-100000.0f)

#define CHUNKS 64
#define SCHUNK (S_ / CHUNKS)   // 128

// Scratch (no allocations allowed in kernel_launch)
__device__ float g_qp[B_ * KDIM];                    // projected query + bias, [B,K]
__device__ float g_partial[B_ * CHUNKS * KDIM];      // per-chunk ctx partials

// HW tanh (sm_75+): MUFU-class, ~16cyc lat, abs err ~5e-4 — removes the
// ~15-instr FMA polynomial of tanhf from the k_energy critical path.
__device__ __forceinline__ float tanh_hw(float x)
{
    float y;
    asm("tanh.approx.f32 %0, %1;" : "=f"(y) : "f"(x));
    return y;
}

// ---------------------------------------------------------------------------
// Kernel 1: qp[b,k] = b_attr[k] + sum_q query[b,q] * W[k,q]
// one warp per (b,k); W row contiguous over q -> coalesced float4 loads
// ---------------------------------------------------------------------------
__global__ void k_proj(const float* __restrict__ query,
                       const float* __restrict__ W,
                       const float* __restrict__ bvec)
{
    int gw   = (blockIdx.x * blockDim.x + threadIdx.x) >> 5;
    int lane = threadIdx.x & 31;
    if (gw >= B_ * KDIM) return;
    int b = gw / KDIM;
    int k = gw % KDIM;

    const float4* qrow = (const float4*)(query + (size_t)b * QDIM);
    const float4* wrow = (const float4*)(W + (size_t)k * QDIM);

    float acc = 0.f;
#pragma unroll
    for (int j = 0; j < QDIM / (32 * 4); j++) {      // 8 iters
        float4 q4 = qrow[lane + j * 32];
        float4 w4 = wrow[lane + j * 32];
        acc += q4.x * w4.x + q4.y * w4.y + q4.z * w4.z + q4.w * w4.w;
    }
#pragma unroll
    for (int o = 16; o; o >>= 1) acc += __shfl_xor_sync(0xFFFFFFFFu, acc, o);
    if (lane == 0) g_qp[b * KDIM + k] = acc + bvec[k];
}

// ---------------------------------------------------------------------------
// Kernel 2: energies[b,s] = mask*dot(tanh(keys[b,s,:]+qp[b,:]), V) + (1-mask)*MIN
// one warp per (b,s) row; K=256 -> 2 float4 loads per lane; HW tanh.
// ---------------------------------------------------------------------------
__global__ void k_energy(const float* __restrict__ keys,
                         const float* __restrict__ mask,
                         const float* __restrict__ Vvec,
                         float* __restrict__ energies)
{
    int gw   = (blockIdx.x * blockDim.x + threadIdx.x) >> 5;
    int lane = threadIdx.x & 31;
    if (gw >= B_ * S_) return;
    int b = gw / S_;

    const float* row = keys + (size_t)gw * KDIM;
    const float* qp  = g_qp + b * KDIM;

    // Batch both key loads up front (2 LDG.128 in flight per lane)
    float4 kv0 = *(const float4*)(row + lane * 4);
    float4 kv1 = *(const float4*)(row + lane * 4 + 128);
    float4 qv0 = *(const float4*)(qp + lane * 4);
    float4 qv1 = *(const float4*)(qp + lane * 4 + 128);
    float4 vv0 = *(const float4*)(Vvec + lane * 4);
    float4 vv1 = *(const float4*)(Vvec + lane * 4 + 128);

    float acc = 0.f;
    acc += tanh_hw(kv0.x + qv0.x) * vv0.x;
    acc += tanh_hw(kv0.y + qv0.y) * vv0.y;
    acc += tanh_hw(kv0.z + qv0.z) * vv0.z;
    acc += tanh_hw(kv0.w + qv0.w) * vv0.w;
    acc += tanh_hw(kv1.x + qv1.x) * vv1.x;
    acc += tanh_hw(kv1.y + qv1.y) * vv1.y;
    acc += tanh_hw(kv1.z + qv1.z) * vv1.z;
    acc += tanh_hw(kv1.w + qv1.w) * vv1.w;

#pragma unroll
    for (int o = 16; o; o >>= 1) acc += __shfl_xor_sync(0xFFFFFFFFu, acc, o);

    if (lane == 0) {
        float m = mask[gw];
        energies[gw] = m * acc + (1.0f - m) * FLOAT_MIN_V;
    }
}

// ---------------------------------------------------------------------------
// Kernel 3: in-place softmax over S per batch. One block of 1024 per batch,
// 8 elements per thread.
// ---------------------------------------------------------------------------
__global__ void k_softmax(float* __restrict__ scores)
{
    __shared__ float red[32];
    int b   = blockIdx.x;
    int tid = threadIdx.x;
    float* e = scores + (size_t)b * S_;

    float v[8];
    float mx = -INFINITY;
#pragma unroll
    for (int i = 0; i < 8; i++) {
        v[i] = e[tid + i * 1024];
        mx = fmaxf(mx, v[i]);
    }
#pragma unroll
    for (int o = 16; o; o >>= 1) mx = fmaxf(mx, __shfl_xor_sync(0xFFFFFFFFu, mx, o));
    if ((tid & 31) == 0) red[tid >> 5] = mx;
    __syncthreads();
    if (tid < 32) {
        float t = red[tid];
#pragma unroll
        for (int o = 16; o; o >>= 1) t = fmaxf(t, __shfl_xor_sync(0xFFFFFFFFu, t, o));
        red[tid] = t;
    }
    __syncthreads();
    mx = red[0];

    float sum = 0.f;
#pragma unroll
    for (int i = 0; i < 8; i++) {
        v[i] = __expf(v[i] - mx);
        sum += v[i];
    }
    __syncthreads();
#pragma unroll
    for (int o = 16; o; o >>= 1) sum += __shfl_xor_sync(0xFFFFFFFFu, sum, o);
    if ((tid & 31) == 0) red[tid >> 5] = sum;
    __syncthreads();
    if (tid < 32) {
        float t = red[tid];
#pragma unroll
        for (int o = 16; o; o >>= 1) t += __shfl_xor_sync(0xFFFFFFFFu, t, o);
        red[tid] = t;
    }
    __syncthreads();
    float inv = 1.0f / red[0];

#pragma unroll
    for (int i = 0; i < 8; i++) e[tid + i * 1024] = v[i] * inv;
}

// ---------------------------------------------------------------------------
// Kernel 4: ctx partials, float4 edition.
// One block per (b, s-chunk). Thread t owns float4-column (t&63) and row
// subset r0=(t>>6), r0+4, r0+8, ... -> all loads are LDG.128, 4x fewer LDGs
// than the scalar version (LSU-issue floor was binding at 55% DRAM).
// Cross-thread (4-way per column) reduce via smem at the end.
// ---------------------------------------------------------------------------
__global__ void k_ctx_partial(const float* __restrict__ values,
                              const float* __restrict__ scores)
{
    int b = blockIdx.x / CHUNKS;
    int c = blockIdx.x % CHUNKS;
    int t = threadIdx.x;                 // 0..255
    int col = t & 63;                    // float4 column within row
    int r0  = t >> 6;                    // 0..3 row phase
    int s0 = c * SCHUNK;

    __shared__ float sc[SCHUNK];
    __shared__ float4 red4[256];

    if (t < SCHUNK)
        sc[t] = scores[(size_t)b * S_ + s0 + t];
    __syncthreads();

    const float4* vp = (const float4*)(values + ((size_t)b * S_ + s0) * KDIM) + col;

    float4 a0 = make_float4(0.f, 0.f, 0.f, 0.f);
    float4 a1 = make_float4(0.f, 0.f, 0.f, 0.f);
    float4 a2 = make_float4(0.f, 0.f, 0.f, 0.f);
    float4 a3 = make_float4(0.f, 0.f, 0.f, 0.f);

    // rows r = r0 + 4*jj, jj = 0..31; 4-wide manual batch, x2 unroll ->
    // 8 LDG.128 in flight per thread.
#pragma unroll 2
    for (int jj = 0; jj < 32; jj += 4) {
        int r_0 = r0 + (jj + 0) * 4;
        int r_1 = r0 + (jj + 1) * 4;
        int r_2 = r0 + (jj + 2) * 4;
        int r_3 = r0 + (jj + 3) * 4;
        float4 v0 = vp[(size_t)r_0 * (KDIM / 4)];
        float4 v1 = vp[(size_t)r_1 * (KDIM / 4)];
        float4 v2 = vp[(size_t)r_2 * (KDIM / 4)];
        float4 v3 = vp[(size_t)r_3 * (KDIM / 4)];
        float s_0 = sc[r_0], s_1 = sc[r_1], s_2 = sc[r_2], s_3 = sc[r_3];
        a0.x += v0.x * s_0; a0.y += v0.y * s_0; a0.z += v0.z * s_0; a0.w += v0.w * s_0;
        a1.x += v1.x * s_1; a1.y += v1.y * s_1; a1.z += v1.z * s_1; a1.w += v1.w * s_1;
        a2.x += v2.x * s_2; a2.y += v2.y * s_2; a2.z += v2.z * s_2; a2.w += v2.w * s_2;
        a3.x += v3.x * s_3; a3.y += v3.y * s_3; a3.z += v3.z * s_3; a3.w += v3.w * s_3;
    }

    float4 acc;
    acc.x = (a0.x + a1.x) + (a2.x + a3.x);
    acc.y = (a0.y + a1.y) + (a2.y + a3.y);
    acc.z = (a0.z + a1.z) + (a2.z + a3.z);
    acc.w = (a0.w + a1.w) + (a2.w + a3.w);

    red4[t] = acc;
    __syncthreads();

    if (t < 64) {
        float4 p0 = red4[t];
        float4 p1 = red4[t + 64];
        float4 p2 = red4[t + 128];
        float4 p3 = red4[t + 192];
        float4 r;
        r.x = (p0.x + p1.x) + (p2.x + p3.x);
        r.y = (p0.y + p1.y) + (p2.y + p3.y);
        r.z = (p0.z + p1.z) + (p2.z + p3.z);
        r.w = (p0.w + p1.w) + (p2.w + p3.w);
        ((float4*)(g_partial + ((size_t)b * CHUNKS + c) * KDIM))[t] = r;
    }
}

// ---------------------------------------------------------------------------
// Kernel 5: reduce partials -> ctx
// ---------------------------------------------------------------------------
__global__ void k_ctx_reduce(float* __restrict__ ctx)
{
    int b = blockIdx.x;
    int k = threadIdx.x;
    float acc = 0.f;
#pragma unroll
    for (int c = 0; c < CHUNKS; c++)
        acc += g_partial[((size_t)b * CHUNKS + c) * KDIM + k];
    ctx[b * KDIM + k] = acc;
}

// ---------------------------------------------------------------------------
// Launch
// inputs (metadata order): query, keys, values, kv_mask, W_attr, b_attr, V_attr
// output: [scores (B*S) | ctx (B*K)]
// ---------------------------------------------------------------------------
extern "C" void kernel_launch(void* const* d_in, const int* in_sizes, int n_in,
                              void* d_out, int out_size)
{
    const float* query = (const float*)d_in[0];
    const float* keys  = (const float*)d_in[1];
    const float* values= (const float*)d_in[2];
    const float* mask  = (const float*)d_in[3];
    const float* W     = (const float*)d_in[4];
    const float* bvec  = (const float*)d_in[5];
    const float* Vvec  = (const float*)d_in[6];

    float* out    = (float*)d_out;
    float* scores = out;                     // B*S
    float* ctx    = out + (size_t)B_ * S_;   // B*K

    // 1) query projection: B*K warps, 8 warps/block
    {
        int warps = B_ * KDIM;
        int blocks = (warps * 32 + 255) / 256;
        k_proj<<<blocks, 256>>>(query, W, bvec);
    }
    // 2) energies: B*S warps, 8 warps/block
    {
        int warps = B_ * S_;
        int blocks = (warps * 32 + 255) / 256;
        k_energy<<<blocks, 256>>>(keys, mask, Vvec, scores);
    }
    // 3) softmax in place
    k_softmax<<<B_, 1024>>>(scores);
    // 4) ctx partials
    k_ctx_partial<<<B_ * CHUNKS, KDIM>>>(values, scores);
    // 5) reduce
    k_ctx_reduce<<<B_, KDIM>>>(ctx);
}